// round 6
// baseline (speedup 1.0000x reference)
#include <cuda_runtime.h>
#include <cstdint>
#include <cstddef>

#define NB    1024
#define CIN   384
#define HWSZ  361
#define P96   96
#define WSTR  100            // padded Wt row stride in floats (400B, 16B-aligned)
#define CHUNK 8              // channels per bulk-copy chunk
#define NCHNK (CIN / CHUNK)  // 48
#define CHF   (CHUNK * HWSZ) // 2888 floats per chunk
#define CHB   (CHF * 4)      // 11552 bytes per chunk

typedef unsigned long long ull;

__device__ __forceinline__ ull pack2(float lo, float hi) {
    ull r; asm("mov.b64 %0, {%1,%2};" : "=l"(r) : "f"(lo), "f"(hi)); return r;
}
__device__ __forceinline__ float2 unpack2(ull v) {
    float2 r; asm("mov.b64 {%0,%1}, %2;" : "=f"(r.x), "=f"(r.y) : "l"(v)); return r;
}
__device__ __forceinline__ ull fma2(ull a, ull b, ull c) {
    ull d; asm("fma.rn.f32x2 %0, %1, %2, %3;" : "=l"(d) : "l"(a), "l"(b), "l"(c)); return d;
}
__device__ __forceinline__ uint32_t smem_u32(const void* p) {
    uint32_t a;
    asm("{ .reg .u64 t; cvta.to.shared.u64 t, %1; cvt.u32.u64 %0, t; }" : "=r"(a) : "l"(p));
    return a;
}
__device__ __forceinline__ void mbar_init(uint32_t mbar, uint32_t cnt) {
    asm volatile("mbarrier.init.shared::cta.b64 [%0], %1;" :: "r"(mbar), "r"(cnt) : "memory");
}
__device__ __forceinline__ void mbar_expect_tx(uint32_t mbar, uint32_t bytes) {
    asm volatile("mbarrier.arrive.expect_tx.shared::cta.b64 _, [%0], %1;"
                 :: "r"(mbar), "r"(bytes) : "memory");
}
__device__ __forceinline__ void mbar_wait(uint32_t mbar, uint32_t parity) {
    asm volatile(
        "{\n\t.reg .pred P;\n\t"
        "W_%=:\n\t"
        "mbarrier.try_wait.parity.acquire.cta.shared::cta.b64 P, [%0], %1;\n\t"
        "@!P bra W_%=;\n\t}"
        :: "r"(mbar), "r"(parity) : "memory");
}
__device__ __forceinline__ void bulk_cp(uint32_t dst_smem, const void* src, uint32_t bytes,
                                        uint32_t mbar) {
    asm volatile(
        "cp.async.bulk.shared::cluster.global.mbarrier::complete_tx::bytes [%0], [%1], %2, [%3];"
        :: "r"(dst_smem), "l"(src), "r"(bytes), "r"(mbar) : "memory");
}

// ---------------------------------------------------------------------------
// One CTA (768 threads) per batch n. Quarter layout (as R5):
//   q = tid/192 : q0 -> p-ch 0..23, q1 -> p-ch 24..47,
//                 q2 -> g-ch 0..23, q3 -> g-ch 24..47
//   s = tid%192 : hw0 = s, hw1 = s+192 (active if s<169)
// x streamed via cp.async.bulk into a 3-deep smem ring; weights smem-resident.
// ---------------------------------------------------------------------------
extern "C" __global__ void __launch_bounds__(768, 1)
k_fused(const float* __restrict__ x, const float* __restrict__ mask,
        const float* __restrict__ msum,
        const float* __restrict__ w1p, const float* __restrict__ w1g,
        const float* __restrict__ betag,
        const float* __restrict__ wling, const float* __restrict__ wlinp,
        const float* __restrict__ blinp, const float* __restrict__ wlinp2,
        const float* __restrict__ beta2, const float* __restrict__ wc2,
        float* __restrict__ out)
{
    __shared__ __align__(8) ull mbars[3];

    extern __shared__ float smem[];
    float* Wt  = smem;                       // [CIN][WSTR]  (padded rows)
    float* xs  = Wt + CIN * WSTR;            // [3][CHF] x ring
    float* rs  = xs + 3 * CHF;               // [12][24] warp partial sums (g)
    float* rm  = rs + 12 * 24;               // [12][24] warp partial maxes (g)
    float* gp  = rm + 12 * 24;               // [144]
    float* hv  = gp + 144;                   // [48]
    float* av  = hv + 48;                    // [48]
    float* wcs = av + 48;                    // [96]
    float* pv  = wcs + 96;                   // [2]
    float* pa0 = pv + 2;                     // [384]
    float* pa1 = pa0 + 384;                  // [384]

    const int n   = blockIdx.x;
    const int tid = threadIdx.x;
    const int q   = tid / 192;
    const int s   = tid % 192;
    const bool act1 = (s < 169);
    const int hw1 = act1 ? (s + 192) : 360;

    const uint32_t mb0 = smem_u32(&mbars[0]);
    const float* xn = x + (size_t)n * CIN * HWSZ;
    const uint32_t xs_sa = smem_u32(xs);

    // init mbarriers + pre-issue first 3 chunks (overlaps weight staging)
    if (tid == 0) {
        mbar_init(mb0, 1);
        mbar_init(mb0 + 8, 1);
        mbar_init(mb0 + 16, 1);
        asm volatile("fence.proxy.async.shared::cta;" ::: "memory");
        #pragma unroll
        for (int i = 0; i < 3; i++) {
            mbar_expect_tx(mb0 + 8 * i, CHB);
            bulk_cp(xs_sa + i * CHB, xn + i * CHF, CHB, mb0 + 8 * i);
        }
    }

    // stage weights transposed into smem (padded stride -> 4-way STS conflicts)
    {
        int p = tid / CIN, c = tid % CIN;
        for (int i = tid; i < P96 * CIN; i += 768) {
            float v = (p < 48) ? w1p[p * CIN + c] : w1g[(p - 48) * CIN + c];
            Wt[c * WSTR + p] = v;
            p += 2;
        }
    }
    if (tid < 96) wcs[tid] = wc2[tid];
    __syncthreads();

    ull acc0[12], acc1[12];
    #pragma unroll
    for (int j = 0; j < 12; j++) { acc0[j] = 0ull; acc1[j] = 0ull; }

    const char* wq = (const char*)Wt + q * 96;    // 24-ch slice, 16B-aligned

    for (int ch = 0; ch < NCHNK; ch++) {
        const int b  = ch % 3;
        const int ph = (ch / 3) & 1;
        mbar_wait(mb0 + 8 * b, ph);

        const float* xb = xs + b * CHF;
        const char* wr  = wq + (ch * CHUNK) * (WSTR * 4);
        #pragma unroll
        for (int cl = 0; cl < CHUNK; cl++) {
            float xv0 = xb[cl * HWSZ + s];
            float xv1 = xb[cl * HWSZ + hw1];
            ull x20 = pack2(xv0, xv0);
            ull x21 = pack2(xv1, xv1);
            const ulonglong2* row = (const ulonglong2*)(wr + cl * (WSTR * 4));
            #pragma unroll
            for (int j = 0; j < 6; j++) {
                ulonglong2 w = row[j];            // LDS.128 broadcast
                acc0[2 * j]     = fma2(x20, w.x, acc0[2 * j]);
                acc0[2 * j + 1] = fma2(x20, w.y, acc0[2 * j + 1]);
                acc1[2 * j]     = fma2(x21, w.x, acc1[2 * j]);
                acc1[2 * j + 1] = fma2(x21, w.y, acc1[2 * j + 1]);
            }
        }
        __syncthreads();                          // all done reading buffer b
        if (ch + 3 < NCHNK && tid == 0) {
            mbar_expect_tx(mb0 + 8 * b, CHB);
            bulk_cp(xs_sa + b * CHB, xn + (ch + 3) * CHF, CHB, mb0 + 8 * b);
        }
    }

    const float m0 = mask[n * HWSZ + s];
    const float m1 = act1 ? mask[n * HWSZ + s + 192] : 0.0f;

    // ---- g-quarters: bias+relu+mask, pooled reduction over 2 hw ----
    if (q >= 2) {
        const int gwarp = (tid >> 5) - 12;
        const int lane  = tid & 31;
        const int gbase = (q - 2) * 24;
        #pragma unroll 4
        for (int gl = 0; gl < 24; gl++) {
            float2 v0 = unpack2(acc0[gl >> 1]);
            float2 v1 = unpack2(acc1[gl >> 1]);
            float r0 = (gl & 1) ? v0.y : v0.x;
            float r1 = (gl & 1) ? v1.y : v1.x;
            float bb = __ldg(&betag[gbase + gl]);
            float u0 = fmaxf((r0 + bb) * m0, 0.0f);
            float u1 = act1 ? fmaxf((r1 + bb) * m1, 0.0f) : 0.0f;
            float sv = u0 + u1;
            float mv = fmaxf(u0 + m0 - 1.0f, act1 ? (u1 + m1 - 1.0f) : -3.0e38f);
            #pragma unroll
            for (int off = 16; off > 0; off >>= 1) {
                sv += __shfl_down_sync(0xffffffffu, sv, off);
                mv  = fmaxf(mv, __shfl_down_sync(0xffffffffu, mv, off));
            }
            if (lane == 0) { rs[gwarp * 24 + gl] = sv; rm[gwarp * 24 + gl] = mv; }
        }
    }
    __syncthreads();

    // ---- pooled features ----
    const float ms = msum[n];
    if (tid < 48) {
        const int wb = (tid < 24) ? 0 : 6;
        const int gl = (tid < 24) ? tid : tid - 24;
        float sum = 0.0f, mx = -3.0e38f;
        #pragma unroll
        for (int w = 0; w < 6; w++) {
            sum += rs[(wb + w) * 24 + gl];
            mx   = fmaxf(mx, rm[(wb + w) * 24 + gl]);
        }
        float mean = sum / ms;
        gp[tid]      = mean;
        gp[48 + tid] = mean * (sqrtf(ms) - 14.0f) * 0.1f;
        gp[96 + tid] = mx;
    }
    __syncthreads();

    // ---- tiny FCs ----
    if (tid < 48) {
        float d1 = 0.0f, d2 = 0.0f;
        const float* wp  = wlinp + tid * 144;
        const float* wgr = wling + tid * 144;
        #pragma unroll 8
        for (int j = 0; j < 144; j++) {
            float g = gp[j];
            d1 += g * wp[j];
            d2 += g * wgr[j];
        }
        hv[tid] = fmaxf(d1 + blinp[tid], 0.0f);
        av[tid] = d2 + beta2[tid];
    }
    __syncthreads();
    if (tid < 2) {
        float p = 0.0f;
        const float* w2 = wlinp2 + tid * 48;
        #pragma unroll
        for (int i = 0; i < 48; i++) p += hv[i] * w2[i];
        pv[tid] = p;
    }
    __syncthreads();

    // ---- p epilogue stage 1: q0 partials (ch 0..23) ----
    if (q == 0) {
        float a0h0 = 0.0f, a1h0 = 0.0f, a0h1 = 0.0f, a1h1 = 0.0f;
        #pragma unroll
        for (int j = 0; j < 12; j++) {
            float2 v0 = unpack2(acc0[j]);
            float2 v1 = unpack2(acc1[j]);
            int c0 = 2 * j, c1 = 2 * j + 1;
            float u;
            u = fmaxf((v0.x + av[c0]) * m0, 0.0f); a0h0 += u * wcs[c0]; a1h0 += u * wcs[48 + c0];
            u = fmaxf((v0.y + av[c1]) * m0, 0.0f); a0h0 += u * wcs[c1]; a1h0 += u * wcs[48 + c1];
            u = fmaxf((v1.x + av[c0]) * m1, 0.0f); a0h1 += u * wcs[c0]; a1h1 += u * wcs[48 + c0];
            u = fmaxf((v1.y + av[c1]) * m1, 0.0f); a0h1 += u * wcs[c1]; a1h1 += u * wcs[48 + c1];
        }
        pa0[s] = a0h0;  pa1[s] = a1h0;
        if (act1) { pa0[s + 192] = a0h1; pa1[s + 192] = a1h1; }
    }
    __syncthreads();

    // ---- p epilogue stage 2: q1 adds ch 24..47, writes output ----
    float* on = out + (size_t)n * 6 * 362;
    if (q == 1) {
        float a0h0 = pa0[s], a1h0 = pa1[s];
        float a0h1 = act1 ? pa0[s + 192] : 0.0f;
        float a1h1 = act1 ? pa1[s + 192] : 0.0f;
        #pragma unroll
        for (int j = 0; j < 12; j++) {
            float2 v0 = unpack2(acc0[j]);
            float2 v1 = unpack2(acc1[j]);
            int c0 = 24 + 2 * j, c1 = 24 + 2 * j + 1;
            float u;
            u = fmaxf((v0.x + av[c0]) * m0, 0.0f); a0h0 += u * wcs[c0]; a1h0 += u * wcs[48 + c0];
            u = fmaxf((v0.y + av[c1]) * m0, 0.0f); a0h0 += u * wcs[c1]; a1h0 += u * wcs[48 + c1];
            u = fmaxf((v1.x + av[c0]) * m1, 0.0f); a0h1 += u * wcs[c0]; a1h1 += u * wcs[48 + c0];
            u = fmaxf((v1.y + av[c1]) * m1, 0.0f); a0h1 += u * wcs[c1]; a1h1 += u * wcs[48 + c1];
        }
        float pen0 = (1.0f - m0) * 5000.0f;
        on[s]           = a0h0 - pen0;
        on[5 * 362 + s] = a1h0 - pen0;
        if (act1) {
            float pen1 = (1.0f - m1) * 5000.0f;
            on[s + 192]           = a0h1 - pen1;
            on[5 * 362 + s + 192] = a1h1 - pen1;
        }
    }
    if (tid == 0) {
        on[361]           = pv[0];
        on[5 * 362 + 361] = pv[1];
    }
    for (int i = tid; i < 4 * 362; i += 768) on[362 + i] = 0.0f;
}

// ---------------------------------------------------------------------------
extern "C" void kernel_launch(void* const* d_in, const int* in_sizes, int n_in,
                              void* d_out, int out_size)
{
    const float* x      = (const float*)d_in[0];
    const float* mask   = (const float*)d_in[1];
    const float* msum   = (const float*)d_in[2];
    const float* w1p    = (const float*)d_in[3];
    const float* w1g    = (const float*)d_in[4];
    const float* betag  = (const float*)d_in[5];
    const float* wling  = (const float*)d_in[6];
    const float* wlinp  = (const float*)d_in[7];
    const float* blinp  = (const float*)d_in[8];
    const float* wlinp2 = (const float*)d_in[9];
    const float* beta2  = (const float*)d_in[10];
    const float* wc2    = (const float*)d_in[11];
    float* out = (float*)d_out;

    const int smem = (CIN * WSTR + 3 * CHF + 12 * 24 * 2 + 144 + 48 + 48 + 96
                      + 2 + 384 * 2) * 4;
    cudaFuncSetAttribute(k_fused,
                         cudaFuncAttributeMaxDynamicSharedMemorySize, smem);

    k_fused<<<NB, 768, smem>>>(x, mask, msum, w1p, w1g, betag,
                               wling, wlinp, blinp, wlinp2, beta2, wc2, out);
}

// round 8
// speedup vs baseline: 1.8524x; 1.8524x over previous
#include <cuda_runtime.h>
#include <cstdint>
#include <cstddef>

#define NB    1024
#define CIN   384
#define HWSZ  361
#define HWP   384              // padded hw
#define WST   100              // W row stride (floats), 400B, 16B-aligned
#define KT    16               // k per tile
#define NT    (CIN / KT)       // 24 tiles

// float offsets in dynamic smem
#define OFF_W    0                       // [384][100]
#define OFF_X    38400                   // [2][16][384]
#define OFF_M    50688                   // [384] mask (padded)
#define OFF_PS   51072                   // [6][48]
#define OFF_PM   51360                   // [6][48]
#define OFF_GP   51648                   // [144]
#define OFF_HV   51792                   // [48]
#define OFF_AV   51840                   // [48]
#define OFF_WC   51888                   // [96]
#define OFF_PV   51984                   // [2]
#define OFF_BETA 51986                   // [48]
#define SMEM_FLOATS 52036
#define SMEM_BYTES  (SMEM_FLOATS * 4)

typedef unsigned long long ull;

__device__ __forceinline__ ull pack2(float lo, float hi) {
    ull r; asm("mov.b64 %0, {%1,%2};" : "=l"(r) : "f"(lo), "f"(hi)); return r;
}
__device__ __forceinline__ float2 unpack2(ull v) {
    float2 r; asm("mov.b64 {%0,%1}, %2;" : "=f"(r.x), "=f"(r.y) : "l"(v)); return r;
}
__device__ __forceinline__ ull fma2(ull a, ull b, ull c) {
    ull d; asm("fma.rn.f32x2 %0, %1, %2, %3;" : "=l"(d) : "l"(a), "l"(b), "l"(c)); return d;
}
__device__ __forceinline__ uint32_t smem_u32(const void* p) {
    uint32_t a;
    asm("{ .reg .u64 t; cvta.to.shared.u64 t, %1; cvt.u32.u64 %0, t; }" : "=r"(a) : "l"(p));
    return a;
}
__device__ __forceinline__ void cp4(uint32_t dst, const void* src, uint32_t sz) {
    asm volatile("cp.async.ca.shared.global [%0], [%1], 4, %2;"
                 :: "r"(dst), "l"(src), "r"(sz) : "memory");
}
__device__ __forceinline__ void cp_commit() {
    asm volatile("cp.async.commit_group;" ::: "memory");
}

// ---------------------------------------------------------------------------
// One CTA (384 thr) per batch n. Register-tiled SGEMM:
//   block 96p x 384hw, warp 48p x 64hw (2 x 6 warps), thread 12p x 8hw.
//   A = W[k][p] smem (padded rows), B = x[k][hw] smem (cp.async ring).
// Then: g-pool -> tiny FCs -> p-epilogue from accumulators.
// ---------------------------------------------------------------------------
extern "C" __global__ void __launch_bounds__(384, 1)
k_policy(const float* __restrict__ x, const float* __restrict__ mask,
         const float* __restrict__ msum,
         const float* __restrict__ w1p, const float* __restrict__ w1g,
         const float* __restrict__ betag,
         const float* __restrict__ wling, const float* __restrict__ wlinp,
         const float* __restrict__ blinp, const float* __restrict__ wlinp2,
         const float* __restrict__ beta2, const float* __restrict__ wc2,
         float* __restrict__ out)
{
    extern __shared__ float smem[];
    float* Wsm  = smem + OFF_W;
    float* Xsm  = smem + OFF_X;
    float* Msm  = smem + OFF_M;
    float* ps   = smem + OFF_PS;
    float* pm   = smem + OFF_PM;
    float* gp   = smem + OFF_GP;
    float* hv   = smem + OFF_HV;
    float* av   = smem + OFF_AV;
    float* wcs  = smem + OFF_WC;
    float* pv   = smem + OFF_PV;
    float* bts  = smem + OFF_BETA;

    const int n    = blockIdx.x;
    const int tid  = threadIdx.x;
    const int warp = tid >> 5;
    const int lane = tid & 31;
    const int wr   = warp / 6;          // 0: p-chans 0..47, 1: g-chans
    const int wc   = warp % 6;          // hw block of 64
    const int tx   = lane & 7;          // hw sub (8 wide)
    const int ty   = lane >> 3;         // p sub (12 wide)

    const float* xn = x + (size_t)n * CIN * HWSZ;
    const uint32_t xs_sa = smem_u32(Xsm);

    // ---- cp.async staging lambda data: thread covers 4 rows x 4 floats ----
    const int crow = tid / 96;                   // 0..3
    const int ccol = (tid % 96) * 4;             // 0..380

    // prologue: issue tiles 0 and 1
    #pragma unroll
    for (int t = 0; t < 2; t++) {
        #pragma unroll
        for (int i = 0; i < 4; i++) {
            const int k = t * KT + crow + 4 * i;
            const uint32_t dst = xs_sa + ((t & 1) * (KT * HWP) + (crow + 4 * i) * HWP + ccol) * 4;
            const float* src = xn + (size_t)k * HWSZ + ccol;
            #pragma unroll
            for (int j = 0; j < 4; j++)
                cp4(dst + 4 * j, src + j, (ccol + j < HWSZ) ? 4u : 0u);
        }
        cp_commit();
    }

    // ---- stage W transposed: Wsm[k][p], thread owns column c = tid ----
    {
        const int c = tid;
        float* wrow = Wsm + c * WST;
        #pragma unroll 4
        for (int p = 0; p < 96; p++)
            wrow[p] = (p < 48) ? w1p[p * CIN + c] : w1g[(p - 48) * CIN + c];
    }
    // small params
    if (tid < 48)  bts[tid] = betag[tid];
    if (tid < 96)  wcs[tid] = wc2[tid];
    if (tid < HWP) Msm[tid] = (tid < HWSZ) ? mask[n * HWSZ + tid] : 0.0f;
    __syncthreads();

    ull acc[12][4];
    #pragma unroll
    for (int i = 0; i < 12; i++)
        #pragma unroll
        for (int j = 0; j < 4; j++) acc[i][j] = 0ull;

    const float* wkb = Wsm + wr * 48 + ty * 12;
    const float* xkb = Xsm + wc * 64 + tx * 8;

    // ---- main loop over 24 k-tiles ----
    for (int t = 0; t < NT; t++) {
        if (t == NT - 1) asm volatile("cp.async.wait_group 0;" ::: "memory");
        else             asm volatile("cp.async.wait_group 1;" ::: "memory");
        __syncthreads();

        const float* wt = wkb + (t * KT) * WST;
        const float* xt = xkb + (t & 1) * (KT * HWP);
        #pragma unroll 4
        for (int kk = 0; kk < KT; kk++) {
            const float4* ap = (const float4*)(wt + kk * WST);
            const ulonglong2* bp = (const ulonglong2*)(xt + kk * HWP);
            float4 A0 = ap[0], A1 = ap[1], A2 = ap[2];
            ulonglong2 bb0 = bp[0], bb1 = bp[1];
            ull b0 = bb0.x, b1 = bb0.y, b2 = bb1.x, b3 = bb1.y;
            #define STEP(AV, IDX) { ull apk = pack2(AV, AV); \
                acc[IDX][0] = fma2(apk, b0, acc[IDX][0]); \
                acc[IDX][1] = fma2(apk, b1, acc[IDX][1]); \
                acc[IDX][2] = fma2(apk, b2, acc[IDX][2]); \
                acc[IDX][3] = fma2(apk, b3, acc[IDX][3]); }
            STEP(A0.x, 0)  STEP(A0.y, 1)  STEP(A0.z, 2)  STEP(A0.w, 3)
            STEP(A1.x, 4)  STEP(A1.y, 5)  STEP(A1.z, 6)  STEP(A1.w, 7)
            STEP(A2.x, 8)  STEP(A2.y, 9)  STEP(A2.z, 10) STEP(A2.w, 11)
            #undef STEP
        }
        __syncthreads();

        if (t + 2 < NT) {
            const int tn = t + 2;
            #pragma unroll
            for (int i = 0; i < 4; i++) {
                const int k = tn * KT + crow + 4 * i;
                const uint32_t dst = xs_sa + ((tn & 1) * (KT * HWP) + (crow + 4 * i) * HWP + ccol) * 4;
                const float* src = xn + (size_t)k * HWSZ + ccol;
                #pragma unroll
                for (int j = 0; j < 4; j++)
                    cp4(dst + 4 * j, src + j, (ccol + j < HWSZ) ? 4u : 0u);
            }
            cp_commit();
        }
    }

    // thread's 8 mask values
    float mv[8];
    {
        const float4* mp = (const float4*)(Msm + wc * 64 + tx * 8);
        float4 m0 = mp[0], m1 = mp[1];
        mv[0]=m0.x; mv[1]=m0.y; mv[2]=m0.z; mv[3]=m0.w;
        mv[4]=m1.x; mv[5]=m1.y; mv[6]=m1.z; mv[7]=m1.w;
    }

    // ---- g-pool: wr==1 warps reduce their 12 g x 8 hw ----
    if (wr == 1) {
        #pragma unroll
        for (int pp = 0; pp < 12; pp++) {
            const int g = ty * 12 + pp;
            const float b = bts[g];
            float s = 0.0f, mx = -3.0e38f;
            #pragma unroll
            for (int hp = 0; hp < 4; hp++) {
                float2 v = unpack2(acc[pp][hp]);
                float u0 = fmaxf((v.x + b) * mv[2*hp],   0.0f);
                float u1 = fmaxf((v.y + b) * mv[2*hp+1], 0.0f);
                s += u0 + u1;
                mx = fmaxf(mx, fmaxf(u0 + mv[2*hp] - 1.0f, u1 + mv[2*hp+1] - 1.0f));
            }
            s  += __shfl_down_sync(0xffffffffu, s, 4);
            mx  = fmaxf(mx, __shfl_down_sync(0xffffffffu, mx, 4));
            s  += __shfl_down_sync(0xffffffffu, s, 2);
            mx  = fmaxf(mx, __shfl_down_sync(0xffffffffu, mx, 2));
            s  += __shfl_down_sync(0xffffffffu, s, 1);
            mx  = fmaxf(mx, __shfl_down_sync(0xffffffffu, mx, 1));
            if (tx == 0) { ps[wc * 48 + g] = s; pm[wc * 48 + g] = mx; }
        }
    }
    __syncthreads();

    // ---- pooled features ----
    const float ms = msum[n];
    if (tid < 48) {
        float s = 0.0f, mx = -3.0e38f;
        #pragma unroll
        for (int w = 0; w < 6; w++) {
            s  += ps[w * 48 + tid];
            mx  = fmaxf(mx, pm[w * 48 + tid]);
        }
        float mean = s / ms;
        gp[tid]      = mean;
        gp[48 + tid] = mean * (sqrtf(ms) - 14.0f) * 0.1f;
        gp[96 + tid] = mx;
    }
    __syncthreads();

    // ---- tiny FCs ----
    if (tid < 48) {
        float d1 = 0.0f, d2 = 0.0f;
        const float* wp  = wlinp + tid * 144;
        const float* wgr = wling + tid * 144;
        #pragma unroll 8
        for (int j = 0; j < 144; j++) {
            float g = gp[j];
            d1 += g * wp[j];
            d2 += g * wgr[j];
        }
        hv[tid] = fmaxf(d1 + blinp[tid], 0.0f);
        av[tid] = d2 + beta2[tid];
    }
    __syncthreads();
    if (tid < 2) {
        float p = 0.0f;
        const float* w2 = wlinp2 + tid * 48;
        #pragma unroll
        for (int i = 0; i < 48; i++) p += hv[i] * w2[i];
        pv[tid] = p;
    }
    __syncthreads();

    // ---- p-epilogue: wr==0 warps, cross-ty reduce, write 2 channels ----
    float* on = out + (size_t)n * 6 * 362;
    if (wr == 0) {
        float a0[8], a1[8];
        #pragma unroll
        for (int h = 0; h < 8; h++) { a0[h] = 0.0f; a1[h] = 0.0f; }
        #pragma unroll
        for (int pp = 0; pp < 12; pp++) {
            const int p = ty * 12 + pp;
            const float ad = av[p];
            const float w0 = wcs[p];
            const float w1 = wcs[48 + p];
            #pragma unroll
            for (int hp = 0; hp < 4; hp++) {
                float2 v = unpack2(acc[pp][hp]);
                float u0 = fmaxf((v.x + ad) * mv[2*hp],   0.0f);
                float u1 = fmaxf((v.y + ad) * mv[2*hp+1], 0.0f);
                a0[2*hp]   += u0 * w0;  a1[2*hp]   += u0 * w1;
                a0[2*hp+1] += u1 * w0;  a1[2*hp+1] += u1 * w1;
            }
        }
        #pragma unroll
        for (int h = 0; h < 8; h++) {
            a0[h] += __shfl_down_sync(0xffffffffu, a0[h], 16);
            a1[h] += __shfl_down_sync(0xffffffffu, a1[h], 16);
            a0[h] += __shfl_down_sync(0xffffffffu, a0[h], 8);
            a1[h] += __shfl_down_sync(0xffffffffu, a1[h], 8);
        }
        if (ty == 0) {
            #pragma unroll
            for (int h = 0; h < 8; h++) {
                const int hw = wc * 64 + tx * 8 + h;
                if (hw < HWSZ) {
                    float pen = (1.0f - mv[h]) * 5000.0f;
                    on[hw]           = a0[h] - pen;
                    on[5 * 362 + hw] = a1[h] - pen;
                }
            }
        }
    }
    if (tid == 0) {
        on[361]           = pv[0];
        on[5 * 362 + 361] = pv[1];
    }
    for (int i = tid; i < 4 * 362; i += 384) on[362 + i] = 0.0f;
}

// ---------------------------------------------------------------------------
extern "C" void kernel_launch(void* const* d_in, const int* in_sizes, int n_in,
                              void* d_out, int out_size)
{
    const float* x      = (const float*)d_in[0];
    const float* mask   = (const float*)d_in[1];
    const float* msum   = (const float*)d_in[2];
    const float* w1p    = (const float*)d_in[3];
    const float* w1g    = (const float*)d_in[4];
    const float* betag  = (const float*)d_in[5];
    const float* wling  = (const float*)d_in[6];
    const float* wlinp  = (const float*)d_in[7];
    const float* blinp  = (const float*)d_in[8];
    const float* wlinp2 = (const float*)d_in[9];
    const float* beta2  = (const float*)d_in[10];
    const float* wc2    = (const float*)d_in[11];
    float* out = (float*)d_out;

    cudaFuncSetAttribute(k_policy,
                         cudaFuncAttributeMaxDynamicSharedMemorySize, SMEM_BYTES);

    k_policy<<<NB, 384, SMEM_BYTES>>>(x, mask, msum, w1p, w1g, betag,
                                      wling, wlinp, blinp, wlinp2, beta2, wc2, out);
}